// round 6
// baseline (speedup 1.0000x reference)
#include <cuda_runtime.h>
#include <math.h>

// Van Rossum distance, single-kernel blocked-scan version.
//   diff = input - target            [1024, 16384] f32
//   y[t] = d*y[t-1] + diff[t]        d = exp(-1/20), per row
//   out  = sqrt( sum(y^2) / 20 )     scalar f32
//
// - Stage rows through shared memory in 4 tiles of 4096 floats so global
//   loads are warp-coalesced float4 (4 L1 lines/instr instead of 32).
//   Padded smem layout p = e + e/16 makes per-thread 16-element reads
//   bank-conflict-free (stride 17, gcd(17,32)=1).
// - Carry across stages held in tid0's register, fed into the per-stage
//   8-warp chain. Chunk contribution: A + 2cB + c^2*C16.
// - Fused final reduction via deterministic last-block pattern (int
//   atomic ticket, fixed-order sum) — removes the second kernel launch.

#define LEN      16384
#define NROWS    1024
#define THREADS  256
#define STAGE    4096                 // elements per smem tile
#define NSTAGES  (LEN / STAGE)        // 4
#define SUB      (STAGE / THREADS)    // 16 elements per thread per stage
#define TILE_PAD (STAGE + STAGE / 16) // 4352 floats (pad 1 per 16)

__device__ float        g_partials[NROWS];
__device__ unsigned int g_ticket = 0;

__global__ __launch_bounds__(THREADS) void vr_kernel(
    const float* __restrict__ inp, const float* __restrict__ tgt,
    float* __restrict__ out)
{
    __shared__ float tile[TILE_PAD];
    __shared__ float warpTot[8];
    __shared__ float warpCarry[8];
    __shared__ float wsum[8];
    __shared__ bool  isLast;

    const int row  = blockIdx.x;
    const int tid  = threadIdx.x;
    const int lane = tid & 31;
    const int warp = tid >> 5;

    // ---- constants (runtime, cheap, float) ----
    const float d  = 0.951229424500714f;     // exp(-1/20)
    const float d2 = d * d;
    float D16 = d;                           // d^16 via 4 squarings
    #pragma unroll
    for (int i = 0; i < 4; i++) D16 = D16 * D16;
    float d2_16 = d2;                        // d2^16
    #pragma unroll
    for (int i = 0; i < 4; i++) d2_16 = d2_16 * d2_16;
    const float C16 = d2 * (1.0f - d2_16) / (1.0f - d2);  // sum_{k=1..16} d^2k
    float D512 = D16;                        // D16^32 = d^512
    #pragma unroll
    for (int i = 0; i < 5; i++) D512 = D512 * D512;
    // Dlane = D16^lane (per-thread constant)
    float Dlane = 1.0f, bsq = D16;
    #pragma unroll
    for (int b = 0; b < 5; b++) {
        if (lane & (1 << b)) Dlane *= bsq;
        bsq *= bsq;
    }

    const float4* __restrict__ ip = (const float4*)(inp + (size_t)row * LEN);
    const float4* __restrict__ tp = (const float4*)(tgt + (size_t)row * LEN);

    float contrib = 0.0f;   // this thread's accumulated sum(y^2) share
    float stage_g = 0.0f;   // tid0 only: scan value entering current stage

    #pragma unroll
    for (int s = 0; s < NSTAGES; s++) {
        // -- coalesced load + diff -> padded smem tile --
        #pragma unroll
        for (int j = 0; j < STAGE / (THREADS * 4); j++) {
            const int v = j * THREADS + tid;            // float4 idx in stage
            float4 a = ip[s * (STAGE / 4) + v];
            float4 b = tp[s * (STAGE / 4) + v];
            const int e = v * 4;                        // e%16 in {0,4,8,12}
            const int p = e + (e >> 4);                 // pad stays constant over 4
            tile[p + 0] = a.x - b.x;
            tile[p + 1] = a.y - b.y;
            tile[p + 2] = a.z - b.z;
            tile[p + 3] = a.w - b.w;
        }
        __syncthreads();

        // -- per-thread local scan of 16 contiguous elements (zero carry-in) --
        float y = 0.0f, A = 0.0f, B = 0.0f, pk = d;
        const int base = tid * 17;                      // conflict-free stride
        #pragma unroll
        for (int k = 0; k < SUB; k++) {
            float x = tile[base + k];
            y = fmaf(d, y, x);
            A = fmaf(y, y, A);
            B = fmaf(y, pk, B);
            pk *= d;
        }

        // -- warp weighted inclusive scan of chunk finals (weight D16) --
        float sI = y;
        float w  = D16;
        #pragma unroll
        for (int off = 1; off < 32; off <<= 1) {
            float up = __shfl_up_sync(0xffffffffu, sI, off);
            if (lane >= off) sI = fmaf(w, up, sI);
            w *= w;
        }
        if (lane == 31) warpTot[warp] = sI;
        __syncthreads();

        // -- cross-warp chain incl. stage carry (tid0 serial, 8 steps) --
        if (tid == 0) {
            float g = stage_g;
            #pragma unroll
            for (int v2 = 0; v2 < 8; v2++) {
                warpCarry[v2] = g;
                g = fmaf(D512, g, warpTot[v2]);
            }
            stage_g = g;                                // carry into next stage
        }
        __syncthreads();

        // -- true carry into this thread's 16-chunk --
        float E = __shfl_up_sync(0xffffffffu, sI, 1);
        if (lane == 0) E = 0.0f;
        const float c = fmaf(Dlane, warpCarry[warp], E);

        // chunk contribution: A + 2cB + c^2 C16
        contrib += fmaf(c, fmaf(c, C16, 2.0f * B), A);
        __syncthreads();   // tile reuse guard for next stage
    }

    // ---- deterministic block reduce ----
    #pragma unroll
    for (int off = 16; off > 0; off >>= 1)
        contrib += __shfl_down_sync(0xffffffffu, contrib, off);
    if (lane == 0) wsum[warp] = contrib;
    __syncthreads();
    if (warp == 0) {
        float v = (lane < 8) ? wsum[lane] : 0.0f;
        #pragma unroll
        for (int off = 4; off > 0; off >>= 1)
            v += __shfl_down_sync(0xffffffffu, v, off);
        if (lane == 0) {
            g_partials[row] = v;
            __threadfence();
            unsigned int t = atomicAdd(&g_ticket, 1u);
            isLast = (t == NROWS - 1);
        }
    }
    __syncthreads();

    // ---- last block: fixed-order global reduce (deterministic) ----
    if (isLast) {
        __threadfence();
        float v = 0.0f;
        #pragma unroll
        for (int j = 0; j < NROWS / THREADS; j++)
            v += ((volatile float*)g_partials)[tid + j * THREADS];

        #pragma unroll
        for (int off = 16; off > 0; off >>= 1)
            v += __shfl_down_sync(0xffffffffu, v, off);
        if (lane == 0) wsum[warp] = v;
        __syncthreads();
        if (warp == 0) {
            float t2 = (lane < 8) ? wsum[lane] : 0.0f;
            #pragma unroll
            for (int off = 4; off > 0; off >>= 1)
                t2 += __shfl_down_sync(0xffffffffu, t2, off);
            if (lane == 0) {
                out[0] = sqrtf(t2 * 0.05f);   // sqrt(sum / TAU * DT)
                g_ticket = 0;                 // reset for next graph replay
            }
        }
    }
}

extern "C" void kernel_launch(void* const* d_in, const int* in_sizes, int n_in,
                              void* d_out, int out_size)
{
    const float* inp = (const float*)d_in[0];
    const float* tgt = (const float*)d_in[1];
    float* out = (float*)d_out;

    vr_kernel<<<NROWS, THREADS>>>(inp, tgt, out);
}

// round 8
// speedup vs baseline: 1.0804x; 1.0804x over previous
#include <cuda_runtime.h>
#include <math.h>

// Van Rossum distance, barrier-free warp-autonomous blocked scan.
//   diff = input - target            [1024, 16384] f32
//   y[t] = d*y[t-1] + diff[t]        d = exp(-1/20), per row
//   out  = sqrt( sum(y^2) / 20 )     scalar f32
//
// R7: no smem staging, no __syncthreads in the main loop.
//  - 1 block (256 thr, 8 warps) per row. Warp w owns contiguous segment
//    [w*2048, (w+1)*2048), processed as 16 iterations of 128 elements.
//  - Coalesced float4 loads give each thread 4 contiguous elements = its
//    scan chunk. Local 4-scan in regs; warp shuffle-scan of chunk totals
//    (weight d^4); iteration carry is one serial fma (weight d^128).
//  - All carry corrections are quadratic in the carry:  A + 2cB + c^2 C.
//    Per-warp segment aggregates (sum-of-squares part, B-moment, total)
//    merge across warps with ONE barrier + tid0 chain (weight d^2048).
//  - Deterministic last-block global reduce (ticket), single launch.

#define LEN      16384
#define NROWS    1024
#define THREADS  256
#define NWARPS   8
#define SEG      (LEN / NWARPS)     // 2048 elements per warp
#define ITERS    (SEG / 128)        // 16 iterations of 128 (32 lanes x 4)

__device__ float        g_partials[NROWS];
__device__ unsigned int g_ticket = 0;

__global__ __launch_bounds__(THREADS) void vr_kernel(
    const float* __restrict__ inp, const float* __restrict__ tgt,
    float* __restrict__ out)
{
    __shared__ float warpA[NWARPS];   // segment sum-of-squares (zero carry-in)
    __shared__ float warpB[NWARPS];   // segment B-moment
    __shared__ float warpT[NWARPS];   // segment-final scan value (zero carry-in)
    __shared__ float wsum[NWARPS];
    __shared__ bool  isLast;

    const int row  = blockIdx.x;
    const int tid  = threadIdx.x;
    const int lane = tid & 31;
    const int warp = tid >> 5;

    // ---- constants ----
    const float d   = 0.951229424500714f;          // exp(-1/20)
    const float d2  = d * d;
    const float D4  = d2 * d2;                     // d^4
    float D128 = D4;                               // d^128 via 5 squarings
    #pragma unroll
    for (int i = 0; i < 5; i++) D128 = D128 * D128;
    float D2048 = D128;                            // d^2048 (~4e-45 ~ 0)
    #pragma unroll
    for (int i = 0; i < 4; i++) D2048 = D2048 * D2048;
    const float C4    = d2 * (1.0f - D4 * D4) / (1.0f - d2);          // sum d^2k, k=1..4
    const float C128  = d2 * (1.0f - D128 * D128) / (1.0f - d2);      // k=1..128
    const float C2048 = d2 / (1.0f - d2);                             // k=1..2048 (d^4096=0)
    // Dl4 = d^(4*lane)
    float Dl4 = 1.0f, bsq = D4;
    #pragma unroll
    for (int b = 0; b < 5; b++) {
        if (lane & (1 << b)) Dl4 *= bsq;
        bsq *= bsq;
    }

    const float4* __restrict__ ip =
        (const float4*)(inp + (size_t)row * LEN) + warp * (SEG / 4) + lane;
    const float4* __restrict__ tp =
        (const float4*)(tgt + (size_t)row * LEN) + warp * (SEG / 4) + lane;

    float contrib = 0.0f;   // sum y^2 share (with within-segment carries folded)
    float BwAcc   = 0.0f;   // per-lane part of segment B-moment
    float W       = 0.0f;   // sum_j K_j * c_j     (uniform across warp)
    float cj      = 0.0f;   // carry into iteration j (uniform across warp)
    float K       = 1.0f;   // d^(128*j)           (uniform across warp)
    float KD      = Dl4;    // K * d^(4*lane)

    #pragma unroll
    for (int j = 0; j < ITERS; j++) {
        float4 a = ip[j * 32];
        float4 b = tp[j * 32];
        float x0 = a.x - b.x, x1 = a.y - b.y, x2 = a.z - b.z, x3 = a.w - b.w;

        // local 4-scan, zero carry-in
        float y0 = x0;
        float y1 = fmaf(d, y0, x1);
        float y2 = fmaf(d, y1, x2);
        float y3 = fmaf(d, y2, x3);

        // A_t = sum y^2 ; B_t = y0 d + y1 d^2 + y2 d^3 + y3 d^4 (Horner)
        float At = fmaf(y3, y3, fmaf(y2, y2, fmaf(y1, y1, y0 * y0)));
        float Bt = d * fmaf(d, fmaf(d, fmaf(d, y3, y2), y1), y0);

        // warp inclusive scan of chunk totals, weight D4
        float sI = y3;
        float w  = D4;
        #pragma unroll
        for (int off = 1; off < 32; off <<= 1) {
            float up = __shfl_up_sync(0xffffffffu, sI, off);
            if (lane >= off) sI = fmaf(w, up, sI);
            w *= w;
        }
        float E = __shfl_up_sync(0xffffffffu, sI, 1);
        if (lane == 0) E = 0.0f;

        // true carry into this thread's chunk
        float c = fmaf(cj, Dl4, E);

        // chunk contribution: At + 2cBt + c^2 C4
        contrib += fmaf(c, fmaf(c, C4, Bt + Bt), At);

        // segment B-moment: KD * (Bt + E*C4)
        BwAcc = fmaf(KD, fmaf(E, C4, Bt), BwAcc);
        W     = fmaf(K, cj, W);

        // serial iteration-carry update
        float Tj = __shfl_sync(0xffffffffu, sI, 31);
        cj = fmaf(D128, cj, Tj);
        K  *= D128;
        KD *= D128;
    }

    // ---- per-warp reduce of contrib and BwAcc ----
    #pragma unroll
    for (int off = 16; off > 0; off >>= 1) {
        contrib += __shfl_down_sync(0xffffffffu, contrib, off);
        BwAcc   += __shfl_down_sync(0xffffffffu, BwAcc, off);
    }
    if (lane == 0) {
        warpA[warp] = contrib;
        warpB[warp] = fmaf(C128, W, BwAcc);  // + carry-induced B terms
        warpT[warp] = cj;                    // segment-final value
    }
    __syncthreads();

    // ---- tid0: chain warp segments, accumulate row total ----
    if (tid == 0) {
        float g = 0.0f, tot = 0.0f;
        #pragma unroll
        for (int v = 0; v < NWARPS; v++) {
            // segment contribution with carry-in g: A + 2gB + g^2 C2048
            tot += fmaf(g, fmaf(g, C2048, 2.0f * warpB[v]), warpA[v]);
            g = fmaf(D2048, g, warpT[v]);
        }
        g_partials[row] = tot;
        __threadfence();
        unsigned int t = atomicAdd(&g_ticket, 1u);
        isLast = (t == NROWS - 1);
    }
    __syncthreads();

    // ---- last block: fixed-order global reduce (deterministic) ----
    if (isLast) {
        __threadfence();
        float v = 0.0f;
        #pragma unroll
        for (int j = 0; j < NROWS / THREADS; j++)
            v += ((volatile float*)g_partials)[tid + j * THREADS];

        #pragma unroll
        for (int off = 16; off > 0; off >>= 1)
            v += __shfl_down_sync(0xffffffffu, v, off);
        if (lane == 0) wsum[warp] = v;
        __syncthreads();
        if (warp == 0) {
            float t2 = (lane < 8) ? wsum[lane] : 0.0f;
            #pragma unroll
            for (int off = 4; off > 0; off >>= 1)
                t2 += __shfl_down_sync(0xffffffffu, t2, off);
            if (lane == 0) {
                out[0] = sqrtf(t2 * 0.05f);   // sqrt(sum / TAU * DT)
                g_ticket = 0;                 // reset for next graph replay
            }
        }
    }
}

extern "C" void kernel_launch(void* const* d_in, const int* in_sizes, int n_in,
                              void* d_out, int out_size)
{
    const float* inp = (const float*)d_in[0];
    const float* tgt = (const float*)d_in[1];
    float* out = (float*)d_out;

    vr_kernel<<<NROWS, THREADS>>>(inp, tgt, out);
}

// round 9
// speedup vs baseline: 1.1562x; 1.0701x over previous
#include <cuda_runtime.h>
#include <math.h>

// Van Rossum distance, barrier-free warp-autonomous blocked scan.
//   diff = input - target            [1024, 16384] f32
//   y[t] = d*y[t-1] + diff[t]        d = exp(-1/20), per row
//   out  = sqrt( sum(y^2) / 20 )     scalar f32
//
// R9 vs R8:
//  - 128-thread blocks (4 warps), one row per block -> ~11 blocks/SM by regs,
//    so all 1024 blocks are co-resident: SINGLE WAVE, no quantized tail
//    (R8's 256-thr blocks gave 6 blocks/SM = 888 slots -> 2 waves, DRAM 54%).
//  - Explicit next-iteration load prefetch to keep >=4 LDG.128 in flight/warp.
//  - Same carry algebra as R8 (warp seg now 4096, ITERS=32; cross-warp merge
//    weight d^4096 ~ 0).

#define LEN      16384
#define NROWS    1024
#define THREADS  128
#define NWARPS   4
#define SEG      (LEN / NWARPS)     // 4096 elements per warp
#define ITERS    (SEG / 128)        // 32 iterations of 128 (32 lanes x 4)

__device__ float        g_partials[NROWS];
__device__ unsigned int g_ticket = 0;

__global__ __launch_bounds__(THREADS) void vr_kernel(
    const float* __restrict__ inp, const float* __restrict__ tgt,
    float* __restrict__ out)
{
    __shared__ float warpA[NWARPS];   // segment sum-of-squares (zero carry-in)
    __shared__ float warpB[NWARPS];   // segment B-moment
    __shared__ float warpT[NWARPS];   // segment-final scan value (zero carry-in)
    __shared__ float wsum[NWARPS];
    __shared__ bool  isLast;

    const int row  = blockIdx.x;
    const int tid  = threadIdx.x;
    const int lane = tid & 31;
    const int warp = tid >> 5;

    // ---- constants ----
    const float d   = 0.951229424500714f;          // exp(-1/20)
    const float d2  = d * d;
    const float D4  = d2 * d2;                     // d^4
    float D128 = D4;                               // d^128 via 5 squarings
    #pragma unroll
    for (int i = 0; i < 5; i++) D128 = D128 * D128;
    float D4096 = D128;                            // d^4096 -> underflows to 0
    #pragma unroll
    for (int i = 0; i < 5; i++) D4096 = D4096 * D4096;
    const float C4    = d2 * (1.0f - D4 * D4) / (1.0f - d2);       // sum d^2k, k=1..4
    const float C128  = d2 * (1.0f - D128 * D128) / (1.0f - d2);   // k=1..128
    const float CBIG  = d2 / (1.0f - d2);                          // k=1..4096 (tail=0)
    // Dl4 = d^(4*lane)
    float Dl4 = 1.0f, bsq = D4;
    #pragma unroll
    for (int b = 0; b < 5; b++) {
        if (lane & (1 << b)) Dl4 *= bsq;
        bsq *= bsq;
    }

    const float4* __restrict__ ip =
        (const float4*)(inp + (size_t)row * LEN) + warp * (SEG / 4) + lane;
    const float4* __restrict__ tp =
        (const float4*)(tgt + (size_t)row * LEN) + warp * (SEG / 4) + lane;

    float contrib = 0.0f;   // sum y^2 share (within-segment carries folded)
    float BwAcc   = 0.0f;   // per-lane part of segment B-moment
    float W       = 0.0f;   // sum_j K_j * c_j     (uniform across warp)
    float cj      = 0.0f;   // carry into iteration j (uniform across warp)
    float K       = 1.0f;   // d^(128*j)           (uniform across warp)
    float KD      = Dl4;    // K * d^(4*lane)

    // prefetch iteration 0
    float4 a = ip[0];
    float4 b = tp[0];

    #pragma unroll
    for (int j = 0; j < ITERS; j++) {
        // prefetch next iteration's loads before touching current data
        float4 an, bn;
        if (j + 1 < ITERS) {
            an = ip[(j + 1) * 32];
            bn = tp[(j + 1) * 32];
        }

        float x0 = a.x - b.x, x1 = a.y - b.y, x2 = a.z - b.z, x3 = a.w - b.w;

        // local 4-scan, zero carry-in
        float y0 = x0;
        float y1 = fmaf(d, y0, x1);
        float y2 = fmaf(d, y1, x2);
        float y3 = fmaf(d, y2, x3);

        // A_t = sum y^2 ; B_t = y0 d + y1 d^2 + y2 d^3 + y3 d^4 (Horner)
        float At = fmaf(y3, y3, fmaf(y2, y2, fmaf(y1, y1, y0 * y0)));
        float Bt = d * fmaf(d, fmaf(d, fmaf(d, y3, y2), y1), y0);

        // warp inclusive scan of chunk totals, weight D4
        float sI = y3;
        float w  = D4;
        #pragma unroll
        for (int off = 1; off < 32; off <<= 1) {
            float up = __shfl_up_sync(0xffffffffu, sI, off);
            if (lane >= off) sI = fmaf(w, up, sI);
            w *= w;
        }
        float E = __shfl_up_sync(0xffffffffu, sI, 1);
        if (lane == 0) E = 0.0f;

        // true carry into this thread's chunk
        float c = fmaf(cj, Dl4, E);

        // chunk contribution: At + 2cBt + c^2 C4
        contrib += fmaf(c, fmaf(c, C4, Bt + Bt), At);

        // segment B-moment: KD * (Bt + E*C4)
        BwAcc = fmaf(KD, fmaf(E, C4, Bt), BwAcc);
        W     = fmaf(K, cj, W);

        // serial iteration-carry update
        float Tj = __shfl_sync(0xffffffffu, sI, 31);
        cj = fmaf(D128, cj, Tj);
        K  *= D128;
        KD *= D128;

        a = an;
        b = bn;
    }

    // ---- per-warp reduce of contrib and BwAcc ----
    #pragma unroll
    for (int off = 16; off > 0; off >>= 1) {
        contrib += __shfl_down_sync(0xffffffffu, contrib, off);
        BwAcc   += __shfl_down_sync(0xffffffffu, BwAcc, off);
    }
    if (lane == 0) {
        warpA[warp] = contrib;
        warpB[warp] = fmaf(C128, W, BwAcc);  // + carry-induced B terms
        warpT[warp] = cj;                    // segment-final value
    }
    __syncthreads();

    // ---- tid0: chain warp segments, accumulate row total ----
    if (tid == 0) {
        float g = 0.0f, tot = 0.0f;
        #pragma unroll
        for (int v = 0; v < NWARPS; v++) {
            // segment contribution with carry-in g: A + 2gB + g^2 CBIG
            tot += fmaf(g, fmaf(g, CBIG, 2.0f * warpB[v]), warpA[v]);
            g = fmaf(D4096, g, warpT[v]);
        }
        g_partials[row] = tot;
        __threadfence();
        unsigned int t = atomicAdd(&g_ticket, 1u);
        isLast = (t == NROWS - 1);
    }
    __syncthreads();

    // ---- last block: fixed-order global reduce (deterministic) ----
    if (isLast) {
        __threadfence();
        float v = 0.0f;
        #pragma unroll
        for (int j = 0; j < NROWS / THREADS; j++)
            v += ((volatile float*)g_partials)[tid + j * THREADS];

        #pragma unroll
        for (int off = 16; off > 0; off >>= 1)
            v += __shfl_down_sync(0xffffffffu, v, off);
        if (lane == 0) wsum[warp] = v;
        __syncthreads();
        if (warp == 0) {
            float t2 = (lane < NWARPS) ? wsum[lane] : 0.0f;
            #pragma unroll
            for (int off = 2; off > 0; off >>= 1)
                t2 += __shfl_down_sync(0xffffffffu, t2, off);
            if (lane == 0) {
                out[0] = sqrtf(t2 * 0.05f);   // sqrt(sum / TAU * DT)
                g_ticket = 0;                 // reset for next graph replay
            }
        }
    }
}

extern "C" void kernel_launch(void* const* d_in, const int* in_sizes, int n_in,
                              void* d_out, int out_size)
{
    const float* inp = (const float*)d_in[0];
    const float* tgt = (const float*)d_in[1];
    float* out = (float*)d_out;

    vr_kernel<<<NROWS, THREADS>>>(inp, tgt, out);
}

// round 10
// speedup vs baseline: 1.1599x; 1.0032x over previous
#include <cuda_runtime.h>
#include <math.h>

// Van Rossum distance, barrier-free warp-autonomous blocked scan.
//   diff = input - target            [1024, 16384] f32
//   y[t] = d*y[t-1] + diff[t]        d = exp(-1/20), per row
//   out  = sqrt( sum(y^2) / 20 )     scalar f32
//
// R10 vs R9: prefetch depth 2 (4 LDG.128 in flight per warp instead of 2).
// Occupancy is grid-limited (1024 blocks x 4 warps / 148 SM = 27.7 warps/SM),
// so the only way to raise in-flight bytes is deeper per-warp MLP:
//   depth 1: ~28 KB/SM in flight ~= latency-BW product (no headroom, DRAM 58%)
//   depth 2: ~55 KB/SM -> 2.2x product, should absorb latency jitter.
// Carry algebra identical to R9 (passed, rel_err 1.16e-7).

#define LEN      16384
#define NROWS    1024
#define THREADS  128
#define NWARPS   4
#define SEG      (LEN / NWARPS)     // 4096 elements per warp
#define ITERS    (SEG / 128)        // 32 iterations of 128 (32 lanes x 4)

__device__ float        g_partials[NROWS];
__device__ unsigned int g_ticket = 0;

__global__ __launch_bounds__(THREADS) void vr_kernel(
    const float* __restrict__ inp, const float* __restrict__ tgt,
    float* __restrict__ out)
{
    __shared__ float warpA[NWARPS];   // segment sum-of-squares (zero carry-in)
    __shared__ float warpB[NWARPS];   // segment B-moment
    __shared__ float warpT[NWARPS];   // segment-final scan value (zero carry-in)
    __shared__ float wsum[NWARPS];
    __shared__ bool  isLast;

    const int row  = blockIdx.x;
    const int tid  = threadIdx.x;
    const int lane = tid & 31;
    const int warp = tid >> 5;

    // ---- constants ----
    const float d   = 0.951229424500714f;          // exp(-1/20)
    const float d2  = d * d;
    const float D4  = d2 * d2;                     // d^4
    float D128 = D4;                               // d^128 via 5 squarings
    #pragma unroll
    for (int i = 0; i < 5; i++) D128 = D128 * D128;
    float D4096 = D128;                            // d^4096 -> underflows to 0
    #pragma unroll
    for (int i = 0; i < 5; i++) D4096 = D4096 * D4096;
    const float C4    = d2 * (1.0f - D4 * D4) / (1.0f - d2);       // sum d^2k, k=1..4
    const float C128  = d2 * (1.0f - D128 * D128) / (1.0f - d2);   // k=1..128
    const float CBIG  = d2 / (1.0f - d2);                          // k=1..4096 (tail=0)
    // Dl4 = d^(4*lane)
    float Dl4 = 1.0f, bsq = D4;
    #pragma unroll
    for (int b = 0; b < 5; b++) {
        if (lane & (1 << b)) Dl4 *= bsq;
        bsq *= bsq;
    }

    const float4* __restrict__ ip =
        (const float4*)(inp + (size_t)row * LEN) + warp * (SEG / 4) + lane;
    const float4* __restrict__ tp =
        (const float4*)(tgt + (size_t)row * LEN) + warp * (SEG / 4) + lane;

    float contrib = 0.0f;   // sum y^2 share (within-segment carries folded)
    float BwAcc   = 0.0f;   // per-lane part of segment B-moment
    float W       = 0.0f;   // sum_j K_j * c_j     (uniform across warp)
    float cj      = 0.0f;   // carry into iteration j (uniform across warp)
    float K       = 1.0f;   // d^(128*j)           (uniform across warp)
    float KD      = Dl4;    // K * d^(4*lane)

    // prefetch iterations 0 and 1 (depth-2 pipeline)
    float4 a0 = ip[0];
    float4 b0 = tp[0];
    float4 a1 = ip[32];
    float4 b1 = tp[32];

    #pragma unroll
    for (int j = 0; j < ITERS; j++) {
        // issue loads for iteration j+2 before touching iteration j's data
        float4 a2, b2;
        if (j + 2 < ITERS) {
            a2 = ip[(j + 2) * 32];
            b2 = tp[(j + 2) * 32];
        }

        float x0 = a0.x - b0.x, x1 = a0.y - b0.y;
        float x2 = a0.z - b0.z, x3 = a0.w - b0.w;

        // local 4-scan, zero carry-in
        float y0 = x0;
        float y1 = fmaf(d, y0, x1);
        float y2 = fmaf(d, y1, x2);
        float y3 = fmaf(d, y2, x3);

        // A_t = sum y^2 ; B_t = y0 d + y1 d^2 + y2 d^3 + y3 d^4 (Horner)
        float At = fmaf(y3, y3, fmaf(y2, y2, fmaf(y1, y1, y0 * y0)));
        float Bt = d * fmaf(d, fmaf(d, fmaf(d, y3, y2), y1), y0);

        // warp inclusive scan of chunk totals, weight D4
        float sI = y3;
        float w  = D4;
        #pragma unroll
        for (int off = 1; off < 32; off <<= 1) {
            float up = __shfl_up_sync(0xffffffffu, sI, off);
            if (lane >= off) sI = fmaf(w, up, sI);
            w *= w;
        }
        float E = __shfl_up_sync(0xffffffffu, sI, 1);
        if (lane == 0) E = 0.0f;

        // true carry into this thread's chunk
        float c = fmaf(cj, Dl4, E);

        // chunk contribution: At + 2cBt + c^2 C4
        contrib += fmaf(c, fmaf(c, C4, Bt + Bt), At);

        // segment B-moment: KD * (Bt + E*C4)
        BwAcc = fmaf(KD, fmaf(E, C4, Bt), BwAcc);
        W     = fmaf(K, cj, W);

        // serial iteration-carry update
        float Tj = __shfl_sync(0xffffffffu, sI, 31);
        cj = fmaf(D128, cj, Tj);
        K  *= D128;
        KD *= D128;

        // rotate prefetch pipeline
        a0 = a1; b0 = b1;
        a1 = a2; b1 = b2;
    }

    // ---- per-warp reduce of contrib and BwAcc ----
    #pragma unroll
    for (int off = 16; off > 0; off >>= 1) {
        contrib += __shfl_down_sync(0xffffffffu, contrib, off);
        BwAcc   += __shfl_down_sync(0xffffffffu, BwAcc, off);
    }
    if (lane == 0) {
        warpA[warp] = contrib;
        warpB[warp] = fmaf(C128, W, BwAcc);  // + carry-induced B terms
        warpT[warp] = cj;                    // segment-final value
    }
    __syncthreads();

    // ---- tid0: chain warp segments, accumulate row total ----
    if (tid == 0) {
        float g = 0.0f, tot = 0.0f;
        #pragma unroll
        for (int v = 0; v < NWARPS; v++) {
            // segment contribution with carry-in g: A + 2gB + g^2 CBIG
            tot += fmaf(g, fmaf(g, CBIG, 2.0f * warpB[v]), warpA[v]);
            g = fmaf(D4096, g, warpT[v]);
        }
        g_partials[row] = tot;
        __threadfence();
        unsigned int t = atomicAdd(&g_ticket, 1u);
        isLast = (t == NROWS - 1);
    }
    __syncthreads();

    // ---- last block: fixed-order global reduce (deterministic) ----
    if (isLast) {
        __threadfence();
        float v = 0.0f;
        #pragma unroll
        for (int j = 0; j < NROWS / THREADS; j++)
            v += ((volatile float*)g_partials)[tid + j * THREADS];

        #pragma unroll
        for (int off = 16; off > 0; off >>= 1)
            v += __shfl_down_sync(0xffffffffu, v, off);
        if (lane == 0) wsum[warp] = v;
        __syncthreads();
        if (warp == 0) {
            float t2 = (lane < NWARPS) ? wsum[lane] : 0.0f;
            #pragma unroll
            for (int off = 2; off > 0; off >>= 1)
                t2 += __shfl_down_sync(0xffffffffu, t2, off);
            if (lane == 0) {
                out[0] = sqrtf(t2 * 0.05f);   // sqrt(sum / TAU * DT)
                g_ticket = 0;                 // reset for next graph replay
            }
        }
    }
}

extern "C" void kernel_launch(void* const* d_in, const int* in_sizes, int n_in,
                              void* d_out, int out_size)
{
    const float* inp = (const float*)d_in[0];
    const float* tgt = (const float*)d_in[1];
    float* out = (float*)d_out;

    vr_kernel<<<NROWS, THREADS>>>(inp, tgt, out);
}